// round 1
// baseline (speedup 1.0000x reference)
#include <cuda_runtime.h>
#include <math.h>

#define N 8192
#define M 8192
#define D 64
#define NIT 20

__device__ __constant__ float c_dummy; // keep nvcc happy about empty constant use

static constexpr float EPS   = 0.05f;
static constexpr float ALPHA = 1.4426950408889634f;   // 1/ln(2)
static constexpr float LN2   = 0.6931471805599453f;
static constexpr float KC    = (2.0f / 0.05f) * 1.4426950408889634f; // (2/eps)*log2(e)

// ---------------- scratch (device globals: allocation-free) ----------------
__device__ float dA [N * M];   // Atilde  = KC * (x @ y^T), row-major [i][j]
__device__ float dAT[N * M];   // Atilde^T, row-major [j][i]
__device__ float d_vt[N];      // v-tilde (log2 domain)
__device__ float d_wt[M];      // w-tilde (log2 domain)
__device__ float d_la[N];      // alpha * log(a/Sa)
__device__ float d_lb[M];      // alpha * log(b/Sb)
__device__ float d_x2[N];
__device__ float d_y2[M];
__device__ float d_an[N];      // a / Sa
__device__ float d_bn[M];      // b / Sb
__device__ float d_sums[2];

// ---------------- row squared norms (warp per row) ----------------
__global__ void k_sqnorm(const float* __restrict__ X, const float* __restrict__ Y) {
    int w    = (blockIdx.x * blockDim.x + threadIdx.x) >> 5;
    int lane = threadIdx.x & 31;
    if (w >= N + M) return;
    const float* src = (w < N) ? (X + (size_t)w * D) : (Y + (size_t)(w - N) * D);
    float v0 = src[lane], v1 = src[lane + 32];
    float s = v0 * v0 + v1 * v1;
    #pragma unroll
    for (int off = 16; off; off >>= 1) s += __shfl_xor_sync(0xffffffffu, s, off);
    if (lane == 0) { if (w < N) d_x2[w] = s; else d_y2[w - N] = s; }
}

// ---------------- sums of a, b ----------------
__global__ void k_sum(const float* __restrict__ a, const float* __restrict__ b) {
    __shared__ float sa[1024], sb[1024];
    int t = threadIdx.x;
    float s1 = 0.f, s2 = 0.f;
    for (int i = t; i < N; i += 1024) s1 += a[i];
    for (int j = t; j < M; j += 1024) s2 += b[j];
    sa[t] = s1; sb[t] = s2; __syncthreads();
    for (int off = 512; off; off >>= 1) {
        if (t < off) { sa[t] += sa[t + off]; sb[t] += sb[t + off]; }
        __syncthreads();
    }
    if (t == 0) { d_sums[0] = sa[0]; d_sums[1] = sb[0]; }
}

// ---------------- init potentials / log weights ----------------
__global__ void k_init(const float* __restrict__ a, const float* __restrict__ b) {
    int i = blockIdx.x * blockDim.x + threadIdx.x;
    if (i >= N) return;
    float lsa = logf(d_sums[0]), lsb = logf(d_sums[1]);
    float ai = a[i];
    d_la[i] = ALPHA * (logf(ai) - lsa);
    d_an[i] = ai / d_sums[0];
    float bi = b[i];
    float lb = ALPHA * (logf(bi) - lsb);
    d_lb[i] = lb;
    d_bn[i] = bi / d_sums[1];
    // g0 = 0  ->  w~_j = alpha*logb_j - (alpha/eps)*y2_j
    d_wt[i] = lb - (ALPHA / EPS) * d_y2[i];
}

// ---------------- prologue GEMM: dA = KC * x@y^T, dAT = transpose ----------------
__global__ void gemm_kernel(const float* __restrict__ X, const float* __restrict__ Y) {
    __shared__ float sx[64][65];
    __shared__ float sy[64][65];
    int t  = threadIdx.x;          // 256 threads
    int tx = t & 15, ty = t >> 4;
    int i0 = blockIdx.y * 64;
    int j0 = blockIdx.x * 64;

    // load tiles: 64 rows x 64 cols each, 4 float4 per thread
    #pragma unroll
    for (int k = 0; k < 4; k++) {
        int q = t + 256 * k;
        int r = q >> 4, c = q & 15;
        float4 fx = *reinterpret_cast<const float4*>(X + (size_t)(i0 + r) * D + c * 4);
        sx[r][c * 4 + 0] = fx.x; sx[r][c * 4 + 1] = fx.y;
        sx[r][c * 4 + 2] = fx.z; sx[r][c * 4 + 3] = fx.w;
        float4 fy = *reinterpret_cast<const float4*>(Y + (size_t)(j0 + r) * D + c * 4);
        sy[r][c * 4 + 0] = fy.x; sy[r][c * 4 + 1] = fy.y;
        sy[r][c * 4 + 2] = fy.z; sy[r][c * 4 + 3] = fy.w;
    }
    __syncthreads();

    float acc[4][4];
    #pragma unroll
    for (int u = 0; u < 4; u++)
        #pragma unroll
        for (int v = 0; v < 4; v++) acc[u][v] = 0.f;

    #pragma unroll 8
    for (int k = 0; k < 64; k++) {
        float av[4], bv[4];
        #pragma unroll
        for (int u = 0; u < 4; u++) av[u] = sx[ty * 4 + u][k];
        #pragma unroll
        for (int v = 0; v < 4; v++) bv[v] = sy[tx * 4 + v][k];
        #pragma unroll
        for (int u = 0; u < 4; u++)
            #pragma unroll
            for (int v = 0; v < 4; v++) acc[u][v] = fmaf(av[u], bv[v], acc[u][v]);
    }

    // write A (coalesced float4)
    #pragma unroll
    for (int u = 0; u < 4; u++) {
        size_t base = (size_t)(i0 + ty * 4 + u) * M + (j0 + tx * 4);
        float4 o = make_float4(acc[u][0] * KC, acc[u][1] * KC, acc[u][2] * KC, acc[u][3] * KC);
        *reinterpret_cast<float4*>(dA + base) = o;
    }

    // transpose through smem (reuse sx) and write AT coalesced
    __syncthreads();
    #pragma unroll
    for (int u = 0; u < 4; u++)
        #pragma unroll
        for (int v = 0; v < 4; v++) sx[tx * 4 + v][ty * 4 + u] = acc[u][v] * KC;
    __syncthreads();
    #pragma unroll
    for (int k = 0; k < 4; k++) {
        int q = t + 256 * k;
        int jj = q >> 4, c = q & 15;
        float4 o = make_float4(sx[jj][c * 4 + 0], sx[jj][c * 4 + 1],
                               sx[jj][c * 4 + 2], sx[jj][c * 4 + 3]);
        *reinterpret_cast<float4*>(dAT + (size_t)(j0 + jj) * N + i0 + c * 4) = o;
    }
}

// ---------------- streaming online log2-sum-exp pass (warp per row) ----------------
// ROWPASS: v~_i = la_i - L2SE_j( w~_j + A[i][j] )
// else   : w~_j = lb_j - L2SE_i( v~_i + AT[j][i] )
template <bool ROWPASS>
__global__ void __launch_bounds__(256) pass_kernel() {
    const float* __restrict__ Mat  = ROWPASS ? dA  : dAT;
    const float* __restrict__ win  = ROWPASS ? d_wt : d_vt;
    const float* __restrict__ lvec = ROWPASS ? d_la : d_lb;
    float*       __restrict__ vout = ROWPASS ? d_vt : d_wt;

    int row  = (blockIdx.x * blockDim.x + threadIdx.x) >> 5;
    int lane = threadIdx.x & 31;
    if (row >= N) return;

    const float4* rowp = reinterpret_cast<const float4*>(Mat + (size_t)row * M);
    const float4* wp   = reinterpret_cast<const float4*>(win);

    float m = -INFINITY, s = 0.f;
    #pragma unroll 4
    for (int c = lane; c < M / 4; c += 32) {
        float4 av = rowp[c];
        float4 wv = wp[c];
        float t0 = av.x + wv.x, t1 = av.y + wv.y, t2 = av.z + wv.z, t3 = av.w + wv.w;
        float lm = fmaxf(fmaxf(t0, t1), fmaxf(t2, t3));
        if (lm <= m) {
            s += (exp2f(t0 - m) + exp2f(t1 - m)) + (exp2f(t2 - m) + exp2f(t3 - m));
        } else {
            s = s * exp2f(m - lm)
              + (exp2f(t0 - lm) + exp2f(t1 - lm)) + (exp2f(t2 - lm) + exp2f(t3 - lm));
            m = lm;
        }
    }
    // warp combine of (m, s)
    #pragma unroll
    for (int off = 16; off; off >>= 1) {
        float m2 = __shfl_xor_sync(0xffffffffu, m, off);
        float s2 = __shfl_xor_sync(0xffffffffu, s, off);
        float nm = fmaxf(m, m2);
        s = s * exp2f(m - nm) + s2 * exp2f(m2 - nm);
        m = nm;
    }
    if (lane == 0) vout[row] = lvec[row] - (m + log2f(s));
}

// ---------------- final reduction ----------------
// f_fin_i = x2_i + eps*ln2*(v~_i - la_i) ; g_fin_j = y2_j + eps*ln2*(w~_j - lb_j)
// out = sum(an * f_fin) + sum(bn * g_fin)
__global__ void k_final(float* __restrict__ out) {
    __shared__ float sm[1024];
    int t = threadIdx.x;
    float s = 0.f;
    for (int i = t; i < N; i += 1024)
        s += d_an[i] * (d_x2[i] + EPS * LN2 * (d_vt[i] - d_la[i]));
    for (int j = t; j < M; j += 1024)
        s += d_bn[j] * (d_y2[j] + EPS * LN2 * (d_wt[j] - d_lb[j]));
    sm[t] = s; __syncthreads();
    for (int off = 512; off; off >>= 1) {
        if (t < off) sm[t] += sm[t + off];
        __syncthreads();
    }
    if (t == 0) out[0] = sm[0];
}

// ---------------- launch ----------------
extern "C" void kernel_launch(void* const* d_in, const int* in_sizes, int n_in,
                              void* d_out, int out_size) {
    const float* a = (const float*)d_in[0];
    const float* x = (const float*)d_in[1];
    const float* b = (const float*)d_in[2];
    const float* y = (const float*)d_in[3];
    float* out = (float*)d_out;

    k_sqnorm<<<(N + M) / 8, 256>>>(x, y);           // warp/row
    k_sum<<<1, 1024>>>(a, b);
    k_init<<<N / 256, 256>>>(a, b);
    gemm_kernel<<<dim3(M / 64, N / 64), 256>>>(x, y);

    for (int it = 0; it < NIT; ++it) {
        pass_kernel<true ><<<(N * 32) / 256, 256>>>();  // v from w (uses A)
        pass_kernel<false><<<(M * 32) / 256, 256>>>();  // w from v (uses AT)
    }
    // final symmetric update: f_fin needs one more row pass; g_fin == g_20 (w unchanged)
    pass_kernel<true><<<(N * 32) / 256, 256>>>();

    k_final<<<1, 1024>>>(out);
}

// round 2
// speedup vs baseline: 1.4140x; 1.4140x over previous
#include <cuda_runtime.h>
#include <math.h>

#define N 8192
#define M 8192
#define D 64
#define NIT 20

static constexpr float EPS   = 0.05f;
static constexpr float ALPHA = 1.4426950408889634f;   // log2(e)
static constexpr float LN2   = 0.6931471805599453f;
static constexpr float KC    = (2.0f / 0.05f) * 1.4426950408889634f; // (2/eps)*log2(e) = 57.7
static constexpr float QS    = 8.0f;        // quantization scale (steps of 0.125 log2 units)
static constexpr float QSI   = 0.125f;      // 1/QS

// ---------------- scratch (device globals: allocation-free) ----------------
__device__ short dA [N * M];   // round(QS * KC * (x@y^T)), row-major [i][j]
__device__ short dAT[N * M];   // transpose, row-major [j][i]
__device__ float d_vt[N];      // v-tilde (log2 domain)
__device__ float d_wt[M];      // w-tilde (log2 domain)
__device__ float d_la[N];      // alpha*log(a/Sa)
__device__ float d_lb[M];
__device__ float d_x2[N];
__device__ float d_y2[M];
__device__ float d_an[N];
__device__ float d_bn[M];
__device__ float d_sums[2];

// ---------------- f32x2 packed helpers ----------------
__device__ __forceinline__ void fma2(unsigned long long& d, unsigned long long a, unsigned long long b) {
    asm("fma.rn.f32x2 %0, %1, %2, %0;" : "+l"(d) : "l"(a), "l"(b));
}
__device__ __forceinline__ unsigned long long bcast2(float a) {
    unsigned long long p;
    asm("mov.b64 %0, {%1, %1};" : "=l"(p) : "f"(a));
    return p;
}
__device__ __forceinline__ void unpack2(unsigned long long p, float& lo, float& hi) {
    asm("mov.b64 {%0, %1}, %2;" : "=f"(lo), "=f"(hi) : "l"(p));
}
__device__ __forceinline__ unsigned long long pack2(float lo, float hi) {
    unsigned long long p;
    asm("mov.b64 %0, {%1, %2};" : "=l"(p) : "f"(lo), "f"(hi));
    return p;
}

__device__ __forceinline__ short quant(float s) {
    float v = fminf(fmaxf(s * (KC * QS), -32600.f), 32600.f);
    return (short)__float2int_rn(v);
}

// ---------------- row squared norms (warp per row) ----------------
__global__ void k_sqnorm(const float* __restrict__ X, const float* __restrict__ Y) {
    int w    = (blockIdx.x * blockDim.x + threadIdx.x) >> 5;
    int lane = threadIdx.x & 31;
    if (w >= N + M) return;
    const float* src = (w < N) ? (X + (size_t)w * D) : (Y + (size_t)(w - N) * D);
    float v0 = src[lane], v1 = src[lane + 32];
    float s = v0 * v0 + v1 * v1;
    #pragma unroll
    for (int off = 16; off; off >>= 1) s += __shfl_xor_sync(0xffffffffu, s, off);
    if (lane == 0) { if (w < N) d_x2[w] = s; else d_y2[w - N] = s; }
}

// ---------------- sums of a, b ----------------
__global__ void k_sum(const float* __restrict__ a, const float* __restrict__ b) {
    __shared__ float sa[1024], sb[1024];
    int t = threadIdx.x;
    float s1 = 0.f, s2 = 0.f;
    for (int i = t; i < N; i += 1024) s1 += a[i];
    for (int j = t; j < M; j += 1024) s2 += b[j];
    sa[t] = s1; sb[t] = s2; __syncthreads();
    for (int off = 512; off; off >>= 1) {
        if (t < off) { sa[t] += sa[t + off]; sb[t] += sb[t + off]; }
        __syncthreads();
    }
    if (t == 0) { d_sums[0] = sa[0]; d_sums[1] = sb[0]; }
}

// ---------------- init potentials / log weights ----------------
__global__ void k_init(const float* __restrict__ a, const float* __restrict__ b) {
    int i = blockIdx.x * blockDim.x + threadIdx.x;
    if (i >= N) return;
    float lsa = logf(d_sums[0]), lsb = logf(d_sums[1]);
    float ai = a[i];
    d_la[i] = ALPHA * (logf(ai) - lsa);
    d_an[i] = ai / d_sums[0];
    float bi = b[i];
    float lb = ALPHA * (logf(bi) - lsb);
    d_lb[i] = lb;
    d_bn[i] = bi / d_sums[1];
    // g0 = 0 -> w~_j = alpha*logb_j - (alpha/eps)*y2_j
    d_wt[i] = lb - (ALPHA / EPS) * d_y2[i];
}

// ---------------- prologue GEMM: dA = quant(KC * x@y^T), dAT = transpose -----
// 64x64 tile, 256 threads, 4x4 per thread, transposed smem + f32x2 FMAs.
__global__ void __launch_bounds__(256) gemm_kernel(const float* __restrict__ X,
                                                   const float* __restrict__ Y) {
    __shared__ float sxT[64][68];   // sxT[k][i]
    __shared__ float syT[64][68];   // syT[k][j]
    int t  = threadIdx.x;
    int tx = t & 15, ty = t >> 4;
    int i0 = blockIdx.y * 64;
    int j0 = blockIdx.x * 64;

    // load + transpose tiles into smem
    #pragma unroll
    for (int k = 0; k < 4; k++) {
        int q = t + 256 * k;
        int r = q >> 4, c = q & 15;
        float4 fx = *reinterpret_cast<const float4*>(X + (size_t)(i0 + r) * D + c * 4);
        sxT[c * 4 + 0][r] = fx.x; sxT[c * 4 + 1][r] = fx.y;
        sxT[c * 4 + 2][r] = fx.z; sxT[c * 4 + 3][r] = fx.w;
        float4 fy = *reinterpret_cast<const float4*>(Y + (size_t)(j0 + r) * D + c * 4);
        syT[c * 4 + 0][r] = fy.x; syT[c * 4 + 1][r] = fy.y;
        syT[c * 4 + 2][r] = fy.z; syT[c * 4 + 3][r] = fy.w;
    }
    __syncthreads();

    unsigned long long acc2[4][2];
    #pragma unroll
    for (int u = 0; u < 4; u++) { acc2[u][0] = 0ull; acc2[u][1] = 0ull; }

    #pragma unroll 8
    for (int k = 0; k < 64; k++) {
        float4 av = *reinterpret_cast<const float4*>(&sxT[k][ty * 4]);
        float4 bv = *reinterpret_cast<const float4*>(&syT[k][tx * 4]);
        unsigned long long b01 = pack2(bv.x, bv.y);
        unsigned long long b23 = pack2(bv.z, bv.w);
        unsigned long long a0 = bcast2(av.x), a1 = bcast2(av.y);
        unsigned long long a2 = bcast2(av.z), a3 = bcast2(av.w);
        fma2(acc2[0][0], a0, b01); fma2(acc2[0][1], a0, b23);
        fma2(acc2[1][0], a1, b01); fma2(acc2[1][1], a1, b23);
        fma2(acc2[2][0], a2, b01); fma2(acc2[2][1], a2, b23);
        fma2(acc2[3][0], a3, b01); fma2(acc2[3][1], a3, b23);
    }

    // quantize
    short qacc[4][4];
    #pragma unroll
    for (int u = 0; u < 4; u++) {
        float v0, v1, v2, v3;
        unpack2(acc2[u][0], v0, v1);
        unpack2(acc2[u][1], v2, v3);
        qacc[u][0] = quant(v0); qacc[u][1] = quant(v1);
        qacc[u][2] = quant(v2); qacc[u][3] = quant(v3);
    }

    // write A (short4, coalesced)
    #pragma unroll
    for (int u = 0; u < 4; u++) {
        size_t base = (size_t)(i0 + ty * 4 + u) * M + (j0 + tx * 4);
        short4 o = make_short4(qacc[u][0], qacc[u][1], qacc[u][2], qacc[u][3]);
        *reinterpret_cast<short4*>(dA + base) = o;
    }

    // transpose through smem (alias sxT) and write AT
    __syncthreads();
    short* ts = reinterpret_cast<short*>(&sxT[0][0]);   // layout ts[j][i], stride 72
    #pragma unroll
    for (int u = 0; u < 4; u++)
        #pragma unroll
        for (int v = 0; v < 4; v++)
            ts[(tx * 4 + v) * 72 + (ty * 4 + u)] = qacc[u][v];
    __syncthreads();
    #pragma unroll
    for (int k = 0; k < 4; k++) {
        int q = t + 256 * k;
        int jj = q >> 4, c = q & 15;
        short4 o = *reinterpret_cast<short4*>(&ts[jj * 72 + c * 4]);
        *reinterpret_cast<short4*>(dAT + (size_t)(j0 + jj) * N + i0 + c * 4) = o;
    }
}

// ---------------- streaming online log2-sum-exp pass (warp per row, int16) ----
// ROWPASS: v~_i = la_i - L2SE_j( 0.125*A[i][j] + w~_j )
// else   : w~_j = lb_j - L2SE_i( 0.125*AT[j][i] + v~_i )
template <bool ROWPASS>
__global__ void __launch_bounds__(256) pass_kernel() {
    const short* __restrict__ Mat  = ROWPASS ? dA  : dAT;
    const float* __restrict__ win  = ROWPASS ? d_wt : d_vt;
    const float* __restrict__ lvec = ROWPASS ? d_la : d_lb;
    float*       __restrict__ vout = ROWPASS ? d_vt : d_wt;

    int row  = (blockIdx.x * blockDim.x + threadIdx.x) >> 5;
    int lane = threadIdx.x & 31;
    if (row >= N) return;

    const int4*   rowp = reinterpret_cast<const int4*>(Mat + (size_t)row * M); // 8 shorts each
    const float4* wp   = reinterpret_cast<const float4*>(win);

    float m = -INFINITY, s = 0.f;
    #pragma unroll 2
    for (int c = lane; c < M / 8; c += 32) {
        int4 pk = rowp[c];
        float4 wa = wp[2 * c], wb = wp[2 * c + 1];
        float t0 = fmaf((float)(short)(pk.x),       QSI, wa.x);
        float t1 = fmaf((float)(pk.x >> 16),        QSI, wa.y);
        float t2 = fmaf((float)(short)(pk.y),       QSI, wa.z);
        float t3 = fmaf((float)(pk.y >> 16),        QSI, wa.w);
        float t4 = fmaf((float)(short)(pk.z),       QSI, wb.x);
        float t5 = fmaf((float)(pk.z >> 16),        QSI, wb.y);
        float t6 = fmaf((float)(short)(pk.w),       QSI, wb.z);
        float t7 = fmaf((float)(pk.w >> 16),        QSI, wb.w);
        float lm = fmaxf(fmaxf(fmaxf(t0, t1), fmaxf(t2, t3)),
                         fmaxf(fmaxf(t4, t5), fmaxf(t6, t7)));
        if (lm > m) {
            s = s * exp2f(m - lm)
              + ((exp2f(t0 - lm) + exp2f(t1 - lm)) + (exp2f(t2 - lm) + exp2f(t3 - lm)))
              + ((exp2f(t4 - lm) + exp2f(t5 - lm)) + (exp2f(t6 - lm) + exp2f(t7 - lm)));
            m = lm;
        } else if (lm > m - 40.f) {   // below: each term < 2^-40, negligible
            s += ((exp2f(t0 - m) + exp2f(t1 - m)) + (exp2f(t2 - m) + exp2f(t3 - m)))
               + ((exp2f(t4 - m) + exp2f(t5 - m)) + (exp2f(t6 - m) + exp2f(t7 - m)));
        }
    }
    // warp combine of (m, s)
    #pragma unroll
    for (int off = 16; off; off >>= 1) {
        float m2 = __shfl_xor_sync(0xffffffffu, m, off);
        float s2 = __shfl_xor_sync(0xffffffffu, s, off);
        float nm = fmaxf(m, m2);
        s = s * exp2f(m - nm) + s2 * exp2f(m2 - nm);
        m = nm;
    }
    if (lane == 0) vout[row] = lvec[row] - (m + log2f(s));
}

// ---------------- final reduction ----------------
__global__ void k_final(float* __restrict__ out) {
    __shared__ float sm[1024];
    int t = threadIdx.x;
    float s = 0.f;
    for (int i = t; i < N; i += 1024)
        s += d_an[i] * (d_x2[i] + EPS * LN2 * (d_vt[i] - d_la[i]));
    for (int j = t; j < M; j += 1024)
        s += d_bn[j] * (d_y2[j] + EPS * LN2 * (d_wt[j] - d_lb[j]));
    sm[t] = s; __syncthreads();
    for (int off = 512; off; off >>= 1) {
        if (t < off) sm[t] += sm[t + off];
        __syncthreads();
    }
    if (t == 0) out[0] = sm[0];
}

// ---------------- launch ----------------
extern "C" void kernel_launch(void* const* d_in, const int* in_sizes, int n_in,
                              void* d_out, int out_size) {
    const float* a = (const float*)d_in[0];
    const float* x = (const float*)d_in[1];
    const float* b = (const float*)d_in[2];
    const float* y = (const float*)d_in[3];
    float* out = (float*)d_out;

    k_sqnorm<<<(N + M) / 8, 256>>>(x, y);
    k_sum<<<1, 1024>>>(a, b);
    k_init<<<N / 256, 256>>>(a, b);
    gemm_kernel<<<dim3(M / 64, N / 64), 256>>>(x, y);

    for (int it = 0; it < NIT; ++it) {
        pass_kernel<true ><<<(N * 32) / 256, 256>>>();  // v from w (uses A)
        pass_kernel<false><<<(M * 32) / 256, 256>>>();  // w from v (uses AT)
    }
    // final symmetric update: f_fin = one more row pass; g_fin == g_20
    pass_kernel<true><<<(N * 32) / 256, 256>>>();

    k_final<<<1, 1024>>>(out);
}

// round 3
// speedup vs baseline: 1.5509x; 1.0968x over previous
#include <cuda_runtime.h>
#include <math.h>

#define N 8192
#define M 8192
#define D 64
#define NIT 20

typedef unsigned long long ull;

static constexpr float EPS   = 0.05f;
static constexpr float ALPHA = 1.4426950408889634f;   // log2(e)
static constexpr float LN2   = 0.6931471805599453f;
static constexpr float KC    = (2.0f / 0.05f) * 1.4426950408889634f; // 57.7
static constexpr float QSI   = 0.125f;      // dequant step
static constexpr float QSF   = 8.0f * KC;   // quant scale applied to raw dot

// ---------------- scratch (device globals) ----------------
__device__ short dA [N * M];   // round(8*KC*(x@y^T)) row-major [i][j]
__device__ short dAT[N * M];   // transpose [j][i]
__device__ float d_vt[N];
__device__ float d_wt[M];
__device__ float d_la[N];
__device__ float d_lb[M];
__device__ float d_x2[N];
__device__ float d_y2[M];
__device__ float d_an[N];
__device__ float d_bn[M];
__device__ float d_sums[2];

// ---------------- f32x2 helpers ----------------
__device__ __forceinline__ void fma2(ull& d, ull a, ull b) {
    asm("fma.rn.f32x2 %0, %1, %2, %0;" : "+l"(d) : "l"(a), "l"(b));
}
__device__ __forceinline__ ull bcast2(float a) {
    ull p; asm("mov.b64 %0, {%1, %1};" : "=l"(p) : "f"(a)); return p;
}
__device__ __forceinline__ void unpack2(ull p, float& lo, float& hi) {
    asm("mov.b64 {%0, %1}, %2;" : "=f"(lo), "=f"(hi) : "l"(p));
}
__device__ __forceinline__ ull pack2(float lo, float hi) {
    ull p; asm("mov.b64 %0, {%1, %2};" : "=l"(p) : "f"(lo), "f"(hi)); return p;
}
__device__ __forceinline__ short quant(float s) {
    float v = fminf(fmaxf(s * QSF, -32600.f), 32600.f);
    return (short)__float2int_rn(v);
}

// ---------------- row squared norms ----------------
__global__ void k_sqnorm(const float* __restrict__ X, const float* __restrict__ Y) {
    int w    = (blockIdx.x * blockDim.x + threadIdx.x) >> 5;
    int lane = threadIdx.x & 31;
    if (w >= N + M) return;
    const float* src = (w < N) ? (X + (size_t)w * D) : (Y + (size_t)(w - N) * D);
    float v0 = src[lane], v1 = src[lane + 32];
    float s = v0 * v0 + v1 * v1;
    #pragma unroll
    for (int off = 16; off; off >>= 1) s += __shfl_xor_sync(0xffffffffu, s, off);
    if (lane == 0) { if (w < N) d_x2[w] = s; else d_y2[w - N] = s; }
}

// ---------------- sums ----------------
__global__ void k_sum(const float* __restrict__ a, const float* __restrict__ b) {
    __shared__ float sa[1024], sb[1024];
    int t = threadIdx.x;
    float s1 = 0.f, s2 = 0.f;
    for (int i = t; i < N; i += 1024) s1 += a[i];
    for (int j = t; j < M; j += 1024) s2 += b[j];
    sa[t] = s1; sb[t] = s2; __syncthreads();
    for (int off = 512; off; off >>= 1) {
        if (t < off) { sa[t] += sa[t + off]; sb[t] += sb[t + off]; }
        __syncthreads();
    }
    if (t == 0) { d_sums[0] = sa[0]; d_sums[1] = sb[0]; }
}

// ---------------- init ----------------
__global__ void k_init(const float* __restrict__ a, const float* __restrict__ b) {
    int i = blockIdx.x * blockDim.x + threadIdx.x;
    if (i >= N) return;
    float lsa = logf(d_sums[0]), lsb = logf(d_sums[1]);
    float ai = a[i];
    d_la[i] = ALPHA * (logf(ai) - lsa);
    d_an[i] = ai / d_sums[0];
    float bi = b[i];
    float lb = ALPHA * (logf(bi) - lsb);
    d_lb[i] = lb;
    d_bn[i] = bi / d_sums[1];
    d_wt[i] = lb - (ALPHA / EPS) * d_y2[i];
}

// ---------------- GEMM: 128x128 tile, 256 thr, 8x8/thread, k-chunk 32 -------
// dA = quant(KC * x@y^T), dAT = transpose.
__global__ void __launch_bounds__(256) gemm_kernel(const float* __restrict__ X,
                                                   const float* __restrict__ Y) {
    __shared__ __align__(16) char sbuf[34816];
    float* sxT = (float*)sbuf;            // [32][132]: sxT[k*132 + i]
    float* syT = sxT + 32 * 132;          // [32][132]: syT[k*132 + j]
    short* ts  = (short*)sbuf;            // [128][136]: ts[j*136 + i]

    int t  = threadIdx.x;
    int tx = t & 15, ty = t >> 4;
    int i0 = blockIdx.y * 128;
    int j0 = blockIdx.x * 128;

    ull acc[8][4];
    #pragma unroll
    for (int u = 0; u < 8; u++)
        #pragma unroll
        for (int v = 0; v < 4; v++) acc[u][v] = 0ull;

    #pragma unroll
    for (int k0 = 0; k0 < 64; k0 += 32) {
        if (k0) __syncthreads();
        // load 128x32 chunks of X and Y, transposed into smem
        #pragma unroll
        for (int it = 0; it < 4; it++) {
            int q = t + 256 * it;
            int r = q >> 3, c = q & 7;           // r: row 0..127, c: float4 col 0..7
            float4 fx = *reinterpret_cast<const float4*>(X + (size_t)(i0 + r) * D + k0 + c * 4);
            sxT[(c * 4 + 0) * 132 + r] = fx.x;
            sxT[(c * 4 + 1) * 132 + r] = fx.y;
            sxT[(c * 4 + 2) * 132 + r] = fx.z;
            sxT[(c * 4 + 3) * 132 + r] = fx.w;
            float4 fy = *reinterpret_cast<const float4*>(Y + (size_t)(j0 + r) * D + k0 + c * 4);
            syT[(c * 4 + 0) * 132 + r] = fy.x;
            syT[(c * 4 + 1) * 132 + r] = fy.y;
            syT[(c * 4 + 2) * 132 + r] = fy.z;
            syT[(c * 4 + 3) * 132 + r] = fy.w;
        }
        __syncthreads();

        #pragma unroll 8
        for (int k = 0; k < 32; k++) {
            float4 a0 = *reinterpret_cast<const float4*>(&sxT[k * 132 + ty * 8]);
            float4 a1 = *reinterpret_cast<const float4*>(&sxT[k * 132 + ty * 8 + 4]);
            float4 b0 = *reinterpret_cast<const float4*>(&syT[k * 132 + tx * 8]);
            float4 b1 = *reinterpret_cast<const float4*>(&syT[k * 132 + tx * 8 + 4]);
            ull bb0 = pack2(b0.x, b0.y), bb1 = pack2(b0.z, b0.w);
            ull bb2 = pack2(b1.x, b1.y), bb3 = pack2(b1.z, b1.w);
            float av[8] = {a0.x, a0.y, a0.z, a0.w, a1.x, a1.y, a1.z, a1.w};
            #pragma unroll
            for (int u = 0; u < 8; u++) {
                ull au = bcast2(av[u]);
                fma2(acc[u][0], au, bb0);
                fma2(acc[u][1], au, bb1);
                fma2(acc[u][2], au, bb2);
                fma2(acc[u][3], au, bb3);
            }
        }
    }

    // quantize 8x8
    short q8[8][8];
    #pragma unroll
    for (int u = 0; u < 8; u++)
        #pragma unroll
        for (int v = 0; v < 4; v++) {
            float lo, hi; unpack2(acc[u][v], lo, hi);
            q8[u][2 * v] = quant(lo); q8[u][2 * v + 1] = quant(hi);
        }

    // write A: each thread 8 int4 stores (rows ty*8+u, cols tx*8..+7)
    #pragma unroll
    for (int u = 0; u < 8; u++) {
        int4 o;
        o.x = (int)(unsigned short)q8[u][0] | ((int)q8[u][1] << 16);
        o.y = (int)(unsigned short)q8[u][2] | ((int)q8[u][3] << 16);
        o.z = (int)(unsigned short)q8[u][4] | ((int)q8[u][5] << 16);
        o.w = (int)(unsigned short)q8[u][6] | ((int)q8[u][7] << 16);
        *reinterpret_cast<int4*>(dA + (size_t)(i0 + ty * 8 + u) * M + j0 + tx * 8) = o;
    }

    // transpose through smem, write AT
    __syncthreads();
    #pragma unroll
    for (int u = 0; u < 8; u++)
        #pragma unroll
        for (int v = 0; v < 8; v++)
            ts[(tx * 8 + v) * 136 + ty * 8 + u] = q8[u][v];
    __syncthreads();
    #pragma unroll
    for (int it = 0; it < 8; it++) {
        int q = t + 256 * it;
        int jj = q >> 4, c = q & 15;
        int4 o = *reinterpret_cast<const int4*>(&ts[jj * 136 + c * 8]);
        *reinterpret_cast<int4*>(dAT + (size_t)(j0 + jj) * N + i0 + c * 8) = o;
    }
}

// ---------------- LSE pass: block = 8 rows, w cached in smem ----------------
// ROWPASS: v~_i = la_i - L2SE_j( 0.125*A[i][j] + w~_j )
template <bool ROWPASS>
__global__ void __launch_bounds__(256) pass_kernel() {
    __shared__ float sw[8192];
    const short* __restrict__ Mat  = ROWPASS ? dA  : dAT;
    const float* __restrict__ win  = ROWPASS ? d_wt : d_vt;
    const float* __restrict__ lvec = ROWPASS ? d_la : d_lb;
    float*       __restrict__ vout = ROWPASS ? d_vt : d_wt;

    int t = threadIdx.x;
    const float4* wp = reinterpret_cast<const float4*>(win);
    #pragma unroll
    for (int it = 0; it < 8; it++) {
        int q = t + 256 * it;
        *reinterpret_cast<float4*>(&sw[q * 4]) = wp[q];
    }
    __syncthreads();

    int warp = t >> 5, lane = t & 31;
    int row  = blockIdx.x * 8 + warp;
    const int4* rowp = reinterpret_cast<const int4*>(Mat + (size_t)row * M);

    float m = -INFINITY, s = 0.f;
    #pragma unroll 1
    for (int c0 = 0; c0 < 1024; c0 += 256) {
        int4 pk[8];
        #pragma unroll
        for (int u = 0; u < 8; u++) pk[u] = rowp[c0 + u * 32 + lane];
        #pragma unroll
        for (int u = 0; u < 8; u++) {
            int e = (c0 + u * 32 + lane) * 8;
            float4 wa = *reinterpret_cast<const float4*>(&sw[e]);
            float4 wb = *reinterpret_cast<const float4*>(&sw[e + 4]);
            float t0 = fmaf((float)(short)(pk[u].x), QSI, wa.x);
            float t1 = fmaf((float)(pk[u].x >> 16),  QSI, wa.y);
            float t2 = fmaf((float)(short)(pk[u].y), QSI, wa.z);
            float t3 = fmaf((float)(pk[u].y >> 16),  QSI, wa.w);
            float t4 = fmaf((float)(short)(pk[u].z), QSI, wb.x);
            float t5 = fmaf((float)(pk[u].z >> 16),  QSI, wb.y);
            float t6 = fmaf((float)(short)(pk[u].w), QSI, wb.z);
            float t7 = fmaf((float)(pk[u].w >> 16),  QSI, wb.w);
            float lm = fmaxf(fmaxf(fmaxf(t0, t1), fmaxf(t2, t3)),
                             fmaxf(fmaxf(t4, t5), fmaxf(t6, t7)));
            if (lm > m) {
                s = s * exp2f(m - lm)
                  + ((exp2f(t0 - lm) + exp2f(t1 - lm)) + (exp2f(t2 - lm) + exp2f(t3 - lm)))
                  + ((exp2f(t4 - lm) + exp2f(t5 - lm)) + (exp2f(t6 - lm) + exp2f(t7 - lm)));
                m = lm;
            } else if (lm > m - 40.f) {
                s += ((exp2f(t0 - m) + exp2f(t1 - m)) + (exp2f(t2 - m) + exp2f(t3 - m)))
                   + ((exp2f(t4 - m) + exp2f(t5 - m)) + (exp2f(t6 - m) + exp2f(t7 - m)));
            }
        }
    }
    #pragma unroll
    for (int off = 16; off; off >>= 1) {
        float m2 = __shfl_xor_sync(0xffffffffu, m, off);
        float s2 = __shfl_xor_sync(0xffffffffu, s, off);
        float nm = fmaxf(m, m2);
        s = s * exp2f(m - nm) + s2 * exp2f(m2 - nm);
        m = nm;
    }
    if (lane == 0) vout[row] = lvec[row] - (m + log2f(s));
}

// ---------------- final reduction ----------------
__global__ void k_final(float* __restrict__ out) {
    __shared__ float sm[1024];
    int t = threadIdx.x;
    float s = 0.f;
    for (int i = t; i < N; i += 1024)
        s += d_an[i] * (d_x2[i] + EPS * LN2 * (d_vt[i] - d_la[i]));
    for (int j = t; j < M; j += 1024)
        s += d_bn[j] * (d_y2[j] + EPS * LN2 * (d_wt[j] - d_lb[j]));
    sm[t] = s; __syncthreads();
    for (int off = 512; off; off >>= 1) {
        if (t < off) sm[t] += sm[t + off];
        __syncthreads();
    }
    if (t == 0) out[0] = sm[0];
}

// ---------------- launch ----------------
extern "C" void kernel_launch(void* const* d_in, const int* in_sizes, int n_in,
                              void* d_out, int out_size) {
    const float* a = (const float*)d_in[0];
    const float* x = (const float*)d_in[1];
    const float* b = (const float*)d_in[2];
    const float* y = (const float*)d_in[3];
    float* out = (float*)d_out;

    k_sqnorm<<<(N + M) / 8, 256>>>(x, y);
    k_sum<<<1, 1024>>>(a, b);
    k_init<<<N / 256, 256>>>(a, b);
    gemm_kernel<<<dim3(M / 128, N / 128), 256>>>(x, y);

    for (int it = 0; it < NIT; ++it) {
        pass_kernel<true ><<<N / 8, 256>>>();  // v from w (A)
        pass_kernel<false><<<M / 8, 256>>>();  // w from v (AT)
    }
    pass_kernel<true><<<N / 8, 256>>>();       // f_fin; g_fin == g_20
    k_final<<<1, 1024>>>(out);
}

// round 4
// speedup vs baseline: 1.7406x; 1.1223x over previous
#include <cuda_runtime.h>
#include <math.h>

#define N 8192
#define M 8192
#define D 64
#define NIT 20

typedef unsigned long long ull;

static constexpr float EPS   = 0.05f;
static constexpr float ALPHA = 1.4426950408889634f;   // log2(e)
static constexpr float LN2   = 0.6931471805599453f;
static constexpr float KC    = (2.0f / 0.05f) * 1.4426950408889634f; // 57.7
static constexpr float QSI   = 0.125f;      // dequant step
static constexpr float QSF   = 8.0f * KC;   // quant scale applied to raw dot

// ---------------- scratch (device globals) ----------------
__device__ short dA [N * M];   // round(8*KC*(x@y^T)) row-major [i][j]
__device__ short dAT[N * M];   // transpose [j][i]
__device__ float d_vt[N];
__device__ float d_wt[M];
__device__ float d_la[N];
__device__ float d_lb[M];
__device__ float d_x2[N];
__device__ float d_y2[M];
__device__ float d_an[N];
__device__ float d_bn[M];
__device__ float d_sums[2];

// ---------------- helpers ----------------
__device__ __forceinline__ float ex2(float x) {        // guaranteed MUFU.EX2
    float r; asm("ex2.approx.f32 %0, %1;" : "=f"(r) : "f"(x)); return r;
}
__device__ __forceinline__ void fma2(ull& d, ull a, ull b) {
    asm("fma.rn.f32x2 %0, %1, %2, %0;" : "+l"(d) : "l"(a), "l"(b));
}
__device__ __forceinline__ ull bcast2(float a) {
    ull p; asm("mov.b64 %0, {%1, %1};" : "=l"(p) : "f"(a)); return p;
}
__device__ __forceinline__ void unpack2(ull p, float& lo, float& hi) {
    asm("mov.b64 {%0, %1}, %2;" : "=f"(lo), "=f"(hi) : "l"(p));
}
__device__ __forceinline__ ull pack2(float lo, float hi) {
    ull p; asm("mov.b64 %0, {%1, %2};" : "=l"(p) : "f"(lo), "f"(hi)); return p;
}
__device__ __forceinline__ short quant(float s) {
    float v = fminf(fmaxf(s * QSF, -32600.f), 32600.f);
    return (short)__float2int_rn(v);
}

// ---------------- row squared norms ----------------
__global__ void k_sqnorm(const float* __restrict__ X, const float* __restrict__ Y) {
    int w    = (blockIdx.x * blockDim.x + threadIdx.x) >> 5;
    int lane = threadIdx.x & 31;
    if (w >= N + M) return;
    const float* src = (w < N) ? (X + (size_t)w * D) : (Y + (size_t)(w - N) * D);
    float v0 = src[lane], v1 = src[lane + 32];
    float s = v0 * v0 + v1 * v1;
    #pragma unroll
    for (int off = 16; off; off >>= 1) s += __shfl_xor_sync(0xffffffffu, s, off);
    if (lane == 0) { if (w < N) d_x2[w] = s; else d_y2[w - N] = s; }
}

// ---------------- sums ----------------
__global__ void k_sum(const float* __restrict__ a, const float* __restrict__ b) {
    __shared__ float sa[1024], sb[1024];
    int t = threadIdx.x;
    float s1 = 0.f, s2 = 0.f;
    for (int i = t; i < N; i += 1024) s1 += a[i];
    for (int j = t; j < M; j += 1024) s2 += b[j];
    sa[t] = s1; sb[t] = s2; __syncthreads();
    for (int off = 512; off; off >>= 1) {
        if (t < off) { sa[t] += sa[t + off]; sb[t] += sb[t + off]; }
        __syncthreads();
    }
    if (t == 0) { d_sums[0] = sa[0]; d_sums[1] = sb[0]; }
}

// ---------------- init ----------------
__global__ void k_init(const float* __restrict__ a, const float* __restrict__ b) {
    int i = blockIdx.x * blockDim.x + threadIdx.x;
    if (i >= N) return;
    float lsa = logf(d_sums[0]), lsb = logf(d_sums[1]);
    float ai = a[i];
    d_la[i] = ALPHA * (logf(ai) - lsa);
    d_an[i] = ai / d_sums[0];
    float bi = b[i];
    float lb = ALPHA * (logf(bi) - lsb);
    d_lb[i] = lb;
    d_bn[i] = bi / d_sums[1];
    d_wt[i] = lb - (ALPHA / EPS) * d_y2[i];
}

// ---------------- GEMM: 128x128 tile, 256 thr, 8x8/thread, k-chunk 32 -------
__global__ void __launch_bounds__(256) gemm_kernel(const float* __restrict__ X,
                                                   const float* __restrict__ Y) {
    __shared__ __align__(16) char sbuf[34816];
    float* sxT = (float*)sbuf;            // [32][132]
    float* syT = sxT + 32 * 132;          // [32][132]
    short* ts  = (short*)sbuf;            // [128][136]

    int t  = threadIdx.x;
    int tx = t & 15, ty = t >> 4;
    int i0 = blockIdx.y * 128;
    int j0 = blockIdx.x * 128;

    ull acc[8][4];
    #pragma unroll
    for (int u = 0; u < 8; u++)
        #pragma unroll
        for (int v = 0; v < 4; v++) acc[u][v] = 0ull;

    #pragma unroll
    for (int k0 = 0; k0 < 64; k0 += 32) {
        if (k0) __syncthreads();
        #pragma unroll
        for (int it = 0; it < 4; it++) {
            int q = t + 256 * it;
            int r = q >> 3, c = q & 7;
            float4 fx = *reinterpret_cast<const float4*>(X + (size_t)(i0 + r) * D + k0 + c * 4);
            sxT[(c * 4 + 0) * 132 + r] = fx.x;
            sxT[(c * 4 + 1) * 132 + r] = fx.y;
            sxT[(c * 4 + 2) * 132 + r] = fx.z;
            sxT[(c * 4 + 3) * 132 + r] = fx.w;
            float4 fy = *reinterpret_cast<const float4*>(Y + (size_t)(j0 + r) * D + k0 + c * 4);
            syT[(c * 4 + 0) * 132 + r] = fy.x;
            syT[(c * 4 + 1) * 132 + r] = fy.y;
            syT[(c * 4 + 2) * 132 + r] = fy.z;
            syT[(c * 4 + 3) * 132 + r] = fy.w;
        }
        __syncthreads();

        #pragma unroll 8
        for (int k = 0; k < 32; k++) {
            float4 a0 = *reinterpret_cast<const float4*>(&sxT[k * 132 + ty * 8]);
            float4 a1 = *reinterpret_cast<const float4*>(&sxT[k * 132 + ty * 8 + 4]);
            float4 b0 = *reinterpret_cast<const float4*>(&syT[k * 132 + tx * 8]);
            float4 b1 = *reinterpret_cast<const float4*>(&syT[k * 132 + tx * 8 + 4]);
            ull bb0 = pack2(b0.x, b0.y), bb1 = pack2(b0.z, b0.w);
            ull bb2 = pack2(b1.x, b1.y), bb3 = pack2(b1.z, b1.w);
            float av[8] = {a0.x, a0.y, a0.z, a0.w, a1.x, a1.y, a1.z, a1.w};
            #pragma unroll
            for (int u = 0; u < 8; u++) {
                ull au = bcast2(av[u]);
                fma2(acc[u][0], au, bb0);
                fma2(acc[u][1], au, bb1);
                fma2(acc[u][2], au, bb2);
                fma2(acc[u][3], au, bb3);
            }
        }
    }

    short q8[8][8];
    #pragma unroll
    for (int u = 0; u < 8; u++)
        #pragma unroll
        for (int v = 0; v < 4; v++) {
            float lo, hi; unpack2(acc[u][v], lo, hi);
            q8[u][2 * v] = quant(lo); q8[u][2 * v + 1] = quant(hi);
        }

    #pragma unroll
    for (int u = 0; u < 8; u++) {
        int4 o;
        o.x = (int)(unsigned short)q8[u][0] | ((int)q8[u][1] << 16);
        o.y = (int)(unsigned short)q8[u][2] | ((int)q8[u][3] << 16);
        o.z = (int)(unsigned short)q8[u][4] | ((int)q8[u][5] << 16);
        o.w = (int)(unsigned short)q8[u][6] | ((int)q8[u][7] << 16);
        *reinterpret_cast<int4*>(dA + (size_t)(i0 + ty * 8 + u) * M + j0 + tx * 8) = o;
    }

    __syncthreads();
    #pragma unroll
    for (int u = 0; u < 8; u++)
        #pragma unroll
        for (int v = 0; v < 8; v++)
            ts[(tx * 8 + v) * 136 + ty * 8 + u] = q8[u][v];
    __syncthreads();
    #pragma unroll
    for (int it = 0; it < 8; it++) {
        int q = t + 256 * it;
        int jj = q >> 4, c = q & 15;
        int4 o = *reinterpret_cast<const int4*>(&ts[jj * 136 + c * 8]);
        *reinterpret_cast<int4*>(dAT + (size_t)(j0 + jj) * N + i0 + c * 8) = o;
    }
}

// ---------------- LSE pass: warp/row, w in smem, uniform control flow -------
// Branchless online LSE + warp-uniform vote skip (no per-lane divergence).
template <bool ROWPASS>
__global__ void __launch_bounds__(256) pass_kernel() {
    __shared__ float sw[8192];
    const short* __restrict__ Mat  = ROWPASS ? dA  : dAT;
    const float* __restrict__ win  = ROWPASS ? d_wt : d_vt;
    const float* __restrict__ lvec = ROWPASS ? d_la : d_lb;
    float*       __restrict__ vout = ROWPASS ? d_vt : d_wt;

    int t = threadIdx.x;
    const float4* wp = reinterpret_cast<const float4*>(win);
    #pragma unroll
    for (int it = 0; it < 8; it++) {
        int q = t + 256 * it;
        *reinterpret_cast<float4*>(&sw[q * 4]) = wp[q];
    }
    __syncthreads();

    int warp = t >> 5, lane = t & 31;
    int row  = blockIdx.x * 8 + warp;
    const int4* rowp = reinterpret_cast<const int4*>(Mat + (size_t)row * M);

    float m = -INFINITY, s = 0.f;

    int4 pk[4];
    #pragma unroll
    for (int u = 0; u < 4; u++) pk[u] = rowp[u * 32 + lane];

    #pragma unroll
    for (int c0 = 0; c0 < 8; c0++) {
        int4 nk[4];
        if (c0 < 7) {
            #pragma unroll
            for (int u = 0; u < 4; u++) nk[u] = rowp[(c0 + 1) * 128 + u * 32 + lane];
        }
        #pragma unroll
        for (int u = 0; u < 4; u++) {
            int e = (c0 * 128 + u * 32 + lane) * 8;
            float4 wa = *reinterpret_cast<const float4*>(&sw[e]);
            float4 wb = *reinterpret_cast<const float4*>(&sw[e + 4]);
            float t0 = fmaf((float)(short)(pk[u].x), QSI, wa.x);
            float t1 = fmaf((float)(pk[u].x >> 16),  QSI, wa.y);
            float t2 = fmaf((float)(short)(pk[u].y), QSI, wa.z);
            float t3 = fmaf((float)(pk[u].y >> 16),  QSI, wa.w);
            float t4 = fmaf((float)(short)(pk[u].z), QSI, wb.x);
            float t5 = fmaf((float)(pk[u].z >> 16),  QSI, wb.y);
            float t6 = fmaf((float)(short)(pk[u].w), QSI, wb.z);
            float t7 = fmaf((float)(pk[u].w >> 16),  QSI, wb.w);
            float lm = fmaxf(fmaxf(fmaxf(t0, t1), fmaxf(t2, t3)),
                             fmaxf(fmaxf(t4, t5), fmaxf(t6, t7)));
            // warp-uniform skip: every skipped term < 2^-40 relative
            if (!__all_sync(0xffffffffu, lm < m - 40.f)) {
                float nm = fmaxf(m, lm);
                float r  = ex2(m - nm);
                float e8 = ((ex2(t0 - nm) + ex2(t1 - nm)) + (ex2(t2 - nm) + ex2(t3 - nm)))
                         + ((ex2(t4 - nm) + ex2(t5 - nm)) + (ex2(t6 - nm) + ex2(t7 - nm)));
                s = fmaf(s, r, e8);
                m = nm;
            }
        }
        if (c0 < 7) {
            #pragma unroll
            for (int u = 0; u < 4; u++) pk[u] = nk[u];
        }
    }

    #pragma unroll
    for (int off = 16; off; off >>= 1) {
        float m2 = __shfl_xor_sync(0xffffffffu, m, off);
        float s2 = __shfl_xor_sync(0xffffffffu, s, off);
        float nm = fmaxf(m, m2);
        s = s * ex2(m - nm) + s2 * ex2(m2 - nm);
        m = nm;
    }
    if (lane == 0) vout[row] = lvec[row] - (m + log2f(s));
}

// ---------------- final reduction ----------------
__global__ void k_final(float* __restrict__ out) {
    __shared__ float sm[1024];
    int t = threadIdx.x;
    float s = 0.f;
    for (int i = t; i < N; i += 1024)
        s += d_an[i] * (d_x2[i] + EPS * LN2 * (d_vt[i] - d_la[i]));
    for (int j = t; j < M; j += 1024)
        s += d_bn[j] * (d_y2[j] + EPS * LN2 * (d_wt[j] - d_lb[j]));
    sm[t] = s; __syncthreads();
    for (int off = 512; off; off >>= 1) {
        if (t < off) sm[t] += sm[t + off];
        __syncthreads();
    }
    if (t == 0) out[0] = sm[0];
}

// ---------------- launch ----------------
extern "C" void kernel_launch(void* const* d_in, const int* in_sizes, int n_in,
                              void* d_out, int out_size) {
    const float* a = (const float*)d_in[0];
    const float* x = (const float*)d_in[1];
    const float* b = (const float*)d_in[2];
    const float* y = (const float*)d_in[3];
    float* out = (float*)d_out;

    k_sqnorm<<<(N + M) / 8, 256>>>(x, y);
    k_sum<<<1, 1024>>>(a, b);
    k_init<<<N / 256, 256>>>(a, b);
    gemm_kernel<<<dim3(M / 128, N / 128), 256>>>(x, y);

    for (int it = 0; it < NIT; ++it) {
        pass_kernel<true ><<<N / 8, 256>>>();  // v from w (A)
        pass_kernel<false><<<M / 8, 256>>>();  // w from v (AT)
    }
    pass_kernel<true><<<N / 8, 256>>>();       // f_fin; g_fin == g_20
    k_final<<<1, 1024>>>(out);
}